// round 1
// baseline (speedup 1.0000x reference)
#include <cuda_runtime.h>

// Fused JPEG round-trip:
// RGB -> YUV -> 8x8 DCT -> quant(round + cubic) -> dequant -> IDCT -> RGB -> normalize
// Input : d_in[0] = float32 [1,3,2048,2048]
// Output: d_out   = float32 [1,3*2048*2048]

#define IMG_W  2048
#define IMG_H  2048
#define PLANE  (IMG_W * IMG_H)
#define TILE_W 256
#define PITCH  257   // PITCH % 32 == 1 -> conflict-free row & column passes

// DCT-II matrix, literals round to the exact fp32 values of the reference
__constant__ float cA[8][8] = {
    { 0.3535533906f,  0.3535533906f,  0.3535533906f,  0.3535533906f,  0.3535533906f,  0.3535533906f,  0.3535533906f,  0.3535533906f},
    { 0.4903926402f,  0.4157348062f,  0.2777851165f,  0.0975451610f, -0.0975451610f, -0.2777851165f, -0.4157348062f, -0.4903926402f},
    { 0.4619397663f,  0.1913417162f, -0.1913417162f, -0.4619397663f, -0.4619397663f, -0.1913417162f,  0.1913417162f,  0.4619397663f},
    { 0.4157348062f, -0.0975451610f, -0.4903926402f, -0.2777851165f,  0.2777851165f,  0.4903926402f,  0.0975451610f, -0.4157348062f},
    { 0.3535533906f, -0.3535533906f, -0.3535533906f,  0.3535533906f,  0.3535533906f, -0.3535533906f, -0.3535533906f,  0.3535533906f},
    { 0.2777851165f, -0.4903926402f,  0.0975451610f,  0.4157348062f, -0.4157348062f, -0.0975451610f,  0.4903926402f, -0.2777851165f},
    { 0.1913417162f, -0.4619397663f,  0.4619397663f, -0.1913417162f, -0.1913417162f,  0.4619397663f, -0.4619397663f,  0.1913417162f},
    { 0.0975451610f, -0.2777851165f,  0.4157348062f, -0.4903926402f,  0.4903926402f, -0.4157348062f,  0.2777851165f, -0.0975451610f}
};

// Quant tables (Q_QUALITY=50 -> scale s = 1.0). [0]=luma, [1]=chroma
__constant__ float cQ[2][64] = {
    { 16,11,10,16,24,40,51,61,
      12,12,14,19,26,58,60,55,
      14,13,16,24,40,57,69,56,
      14,17,22,29,51,87,80,62,
      18,22,37,56,68,109,103,77,
      24,35,55,64,81,104,113,92,
      49,64,78,87,103,121,120,101,
      72,92,95,98,112,100,103,99 },
    { 17,18,24,47,99,99,99,99,
      18,21,26,66,99,99,99,99,
      24,26,56,99,99,99,99,99,
      47,66,99,99,99,99,99,99,
      99,99,99,99,99,99,99,99,
      99,99,99,99,99,99,99,99,
      99,99,99,99,99,99,99,99,
      99,99,99,99,99,99,99,99 }
};

// inv(W) computed analytically in double from the exact reference W entries
#define IW00  1.0f
#define IW01 (-1.2189e-6f)
#define IW02  1.4019996f
#define IW10  1.0f
#define IW11 (-0.34413570f)
#define IW12 (-0.71413614f)
#define IW20  1.0f
#define IW21  1.7720001f
#define IW22  4.0630e-7f

// normalization: out = (rgb/255 - mean/255) * (255/std)
#define MEAN0 0.49137255f   /* 125.3/255 */
#define MEAN1 0.48235294f   /* 123.0/255 */
#define MEAN2 0.44666666f   /* 113.9/255 */
#define ISTD0 4.04761905f   /* 255/63.0 */
#define ISTD1 4.10628019f   /* 255/62.1 */
#define ISTD2 3.82308846f   /* 255/66.7 */

__global__ __launch_bounds__(TILE_W)
void jpeg_roundtrip_kernel(const float* __restrict__ in, float* __restrict__ out)
{
    __shared__ float sm[3][8][PITCH];

    const int tid = threadIdx.x;
    const int gx  = blockIdx.x * TILE_W + tid;
    const int gy0 = blockIdx.y * 8;

    // ---------- load + forward color transform ----------
    #pragma unroll
    for (int r = 0; r < 8; ++r) {
        int idx = (gy0 + r) * IMG_W + gx;
        float R = in[idx];
        float G = in[idx + PLANE];
        float B = in[idx + 2 * PLANE];
        float y = 0.299f * R + 0.587f * G + 0.114f * B;
        float u = fmaf(-0.168736f, R, fmaf(-0.331264f, G, fmaf(0.5f, B, 128.0f)));
        float v = fmaf(0.5f, R, fmaf(-0.418688f, G, fmaf(-0.081312f, B, 128.0f)));
        sm[0][r][tid] = y;
        sm[1][r][tid] = u;
        sm[2][r][tid] = v;
    }
    __syncthreads();

    // ---------- stage A: column pass, t1 = A * B ----------
    #pragma unroll
    for (int ch = 0; ch < 3; ++ch) {
        float v[8], t[8];
        #pragma unroll
        for (int j = 0; j < 8; ++j) v[j] = sm[ch][j][tid];
        #pragma unroll
        for (int i = 0; i < 8; ++i) {
            float s = 0.0f;
            #pragma unroll
            for (int j = 0; j < 8; ++j) s = fmaf(cA[i][j], v[j], s);
            t[i] = s;
        }
        #pragma unroll
        for (int i = 0; i < 8; ++i) sm[ch][i][tid] = t[i];
    }
    __syncthreads();

    const int rr = tid & 7;          // row within 8x8 block
    const int cb = (tid >> 3) * 8;   // column base of this thread's block

    // ---------- stage B: row pass (t1 * A^T) + quant/dequant ----------
    #pragma unroll
    for (int ch = 0; ch < 3; ++ch) {
        const float* qrow = cQ[ch > 0 ? 1 : 0] + rr * 8;
        float v[8];
        #pragma unroll
        for (int k = 0; k < 8; ++k) v[k] = sm[ch][rr][cb + k];
        #pragma unroll
        for (int l = 0; l < 8; ++l) {
            float s = 0.0f;
            #pragma unroll
            for (int k = 0; k < 8; ++k) s = fmaf(v[k], cA[l][k], s);
            float q  = qrow[l];
            float d  = __fdiv_rn(s, q);       // IEEE div, matches reference
            float rn = rintf(d);              // round half-to-even = jnp.round
            float e  = d - rn;
            sm[ch][rr][cb + l] = fmaf(e * e, e, rn) * q;
        }
    }
    __syncthreads();

    // ---------- stage C: column pass, t3 = A^T * X ----------
    #pragma unroll
    for (int ch = 0; ch < 3; ++ch) {
        float v[8], t[8];
        #pragma unroll
        for (int j = 0; j < 8; ++j) v[j] = sm[ch][j][tid];
        #pragma unroll
        for (int i = 0; i < 8; ++i) {
            float s = 0.0f;
            #pragma unroll
            for (int j = 0; j < 8; ++j) s = fmaf(cA[j][i], v[j], s);
            t[i] = s;
        }
        #pragma unroll
        for (int i = 0; i < 8; ++i) sm[ch][i][tid] = t[i];
    }
    __syncthreads();

    // ---------- stage D: row pass, rec = t3 * A ----------
    #pragma unroll
    for (int ch = 0; ch < 3; ++ch) {
        float v[8];
        #pragma unroll
        for (int k = 0; k < 8; ++k) v[k] = sm[ch][rr][cb + k];
        #pragma unroll
        for (int l = 0; l < 8; ++l) {
            float s = 0.0f;
            #pragma unroll
            for (int k = 0; k < 8; ++k) s = fmaf(v[k], cA[k][l], s);
            sm[ch][rr][cb + l] = s;
        }
    }
    __syncthreads();

    // ---------- inverse color transform + normalize + store ----------
    #pragma unroll
    for (int r = 0; r < 8; ++r) {
        float y = sm[0][r][tid];
        float u = sm[1][r][tid] - 128.0f;
        float v = sm[2][r][tid] - 128.0f;
        float R = fmaf(IW01, u, fmaf(IW02, v, IW00 * y));
        float G = fmaf(IW11, u, fmaf(IW12, v, IW10 * y));
        float B = fmaf(IW21, u, fmaf(IW22, v, IW20 * y));
        int idx = (gy0 + r) * IMG_W + gx;
        out[idx]             = (R * (1.0f / 255.0f) - MEAN0) * ISTD0;
        out[idx + PLANE]     = (G * (1.0f / 255.0f) - MEAN1) * ISTD1;
        out[idx + 2 * PLANE] = (B * (1.0f / 255.0f) - MEAN2) * ISTD2;
    }
}

extern "C" void kernel_launch(void* const* d_in, const int* in_sizes, int n_in,
                              void* d_out, int out_size)
{
    const float* in = (const float*)d_in[0];
    float* out = (float*)d_out;
    dim3 grid(IMG_W / TILE_W, IMG_H / 8);
    dim3 block(TILE_W);
    jpeg_roundtrip_kernel<<<grid, block>>>(in, out);
}

// round 2
// speedup vs baseline: 1.3070x; 1.3070x over previous
#include <cuda_runtime.h>

// Fused JPEG round-trip, register-resident 8x8 blocks + butterflied DCT.
// Input : d_in[0] = float32 [1,3,2048,2048]
// Output: d_out   = float32 [1,3*2048*2048]

#define IMG_W  2048
#define IMG_H  2048
#define PLANE  (IMG_W * IMG_H)
#define TW     512            // tile width (pixels)
#define TH     8              // tile height (one block row)
#define NTHREADS 192          // 64 blocks/channel * 3 channels
#define NGROUPS (TH * TW / 4) // 1024 float4 pixel groups per tile

// DCT basis constants (fp32 round of the reference matrix entries)
#define C1 0.4903926402f
#define C2 0.4619397663f
#define C3 0.4157348062f
#define C4 0.3535533906f
#define C5 0.2777851165f
#define C6 0.1913417162f
#define C7 0.0975451610f

// Quant tables (Q=50 -> s=1). [0]=luma, [1]=chroma
__constant__ float cQ[2][64] = {
    { 16,11,10,16,24,40,51,61,
      12,12,14,19,26,58,60,55,
      14,13,16,24,40,57,69,56,
      14,17,22,29,51,87,80,62,
      18,22,37,56,68,109,103,77,
      24,35,55,64,81,104,113,92,
      49,64,78,87,103,121,120,101,
      72,92,95,98,112,100,103,99 },
    { 17,18,24,47,99,99,99,99,
      18,21,26,66,99,99,99,99,
      24,26,56,99,99,99,99,99,
      47,66,99,99,99,99,99,99,
      99,99,99,99,99,99,99,99,
      99,99,99,99,99,99,99,99,
      99,99,99,99,99,99,99,99,
      99,99,99,99,99,99,99,99 }
};

// Correctly-rounded fp32 reciprocals (compile-time IEEE division)
__constant__ float cRQ[2][64] = {
    { 1.f/16,1.f/11,1.f/10,1.f/16,1.f/24,1.f/40,1.f/51,1.f/61,
      1.f/12,1.f/12,1.f/14,1.f/19,1.f/26,1.f/58,1.f/60,1.f/55,
      1.f/14,1.f/13,1.f/16,1.f/24,1.f/40,1.f/57,1.f/69,1.f/56,
      1.f/14,1.f/17,1.f/22,1.f/29,1.f/51,1.f/87,1.f/80,1.f/62,
      1.f/18,1.f/22,1.f/37,1.f/56,1.f/68,1.f/109,1.f/103,1.f/77,
      1.f/24,1.f/35,1.f/55,1.f/64,1.f/81,1.f/104,1.f/113,1.f/92,
      1.f/49,1.f/64,1.f/78,1.f/87,1.f/103,1.f/121,1.f/120,1.f/101,
      1.f/72,1.f/92,1.f/95,1.f/98,1.f/112,1.f/100,1.f/103,1.f/99 },
    { 1.f/17,1.f/18,1.f/24,1.f/47,1.f/99,1.f/99,1.f/99,1.f/99,
      1.f/18,1.f/21,1.f/26,1.f/66,1.f/99,1.f/99,1.f/99,1.f/99,
      1.f/24,1.f/26,1.f/56,1.f/99,1.f/99,1.f/99,1.f/99,1.f/99,
      1.f/47,1.f/66,1.f/99,1.f/99,1.f/99,1.f/99,1.f/99,1.f/99,
      1.f/99,1.f/99,1.f/99,1.f/99,1.f/99,1.f/99,1.f/99,1.f/99,
      1.f/99,1.f/99,1.f/99,1.f/99,1.f/99,1.f/99,1.f/99,1.f/99,
      1.f/99,1.f/99,1.f/99,1.f/99,1.f/99,1.f/99,1.f/99,1.f/99,
      1.f/99,1.f/99,1.f/99,1.f/99,1.f/99,1.f/99,1.f/99,1.f/99 }
};

// inv(W) (double-precision analytic inverse of the reference W, rounded)
#define IW01 (-1.2189e-6f)
#define IW02  1.4019996f
#define IW11 (-0.34413570f)
#define IW12 (-0.71413614f)
#define IW21  1.7720001f
#define IW22  4.0630e-7f

#define MEAN0 0.49137255f
#define MEAN1 0.48235294f
#define MEAN2 0.44666666f
#define ISTD0 4.04761905f
#define ISTD1 4.10628019f
#define ISTD2 3.82308846f

// 8-point DCT-II (even/odd butterfly), in place
__device__ __forceinline__ void fdct8(float v[8])
{
    float e0 = v[0] + v[7], e1 = v[1] + v[6], e2 = v[2] + v[5], e3 = v[3] + v[4];
    float o0 = v[0] - v[7], o1 = v[1] - v[6], o2 = v[2] - v[5], o3 = v[3] - v[4];
    float s03 = e0 + e3, s12 = e1 + e2;
    float d03 = e0 - e3, d12 = e1 - e2;
    v[0] = C4 * (s03 + s12);
    v[4] = C4 * (s03 - s12);
    v[2] = fmaf(C2, d03,  C6 * d12);
    v[6] = fmaf(C6, d03, -C2 * d12);
    v[1] = fmaf(C1, o0, fmaf( C3, o1, fmaf( C5, o2,  C7 * o3)));
    v[3] = fmaf(C3, o0, fmaf(-C7, o1, fmaf(-C1, o2, -C5 * o3)));
    v[5] = fmaf(C5, o0, fmaf(-C1, o1, fmaf( C7, o2,  C3 * o3)));
    v[7] = fmaf(C7, o0, fmaf(-C5, o1, fmaf( C3, o2, -C1 * o3)));
}

// 8-point inverse (A^T on the left / A on the right), in place
__device__ __forceinline__ void idct8(float v[8])
{
    float sp = C4 * (v[0] + v[4]);
    float sm = C4 * (v[0] - v[4]);
    float t1 = fmaf(C2, v[2],  C6 * v[6]);
    float t2 = fmaf(C6, v[2], -C2 * v[6]);
    float E0 = sp + t1, E1 = sm + t2, E2 = sm - t2, E3 = sp - t1;
    float O0 = fmaf(C1, v[1], fmaf( C3, v[3], fmaf( C5, v[5],  C7 * v[7])));
    float O1 = fmaf(C3, v[1], fmaf(-C7, v[3], fmaf(-C1, v[5], -C5 * v[7])));
    float O2 = fmaf(C5, v[1], fmaf(-C1, v[3], fmaf( C7, v[5],  C3 * v[7])));
    float O3 = fmaf(C7, v[1], fmaf(-C5, v[3], fmaf( C3, v[5], -C1 * v[7])));
    v[0] = E0 + O0;  v[7] = E0 - O0;
    v[1] = E1 + O1;  v[6] = E1 - O1;
    v[2] = E2 + O2;  v[5] = E2 - O2;
    v[3] = E3 + O3;  v[4] = E3 - O3;
}

__global__ __launch_bounds__(NTHREADS)
void jpeg_roundtrip_kernel(const float* __restrict__ in, float* __restrict__ out)
{
    __shared__ __align__(16) float s[3][TH][TW];

    const int tid = threadIdx.x;
    const int gx0 = blockIdx.x * TW;
    const int gy0 = blockIdx.y * TH;

    // ---------- load + forward color (float4 granularity) ----------
    #pragma unroll
    for (int it = 0; it < 6; ++it) {
        int g = tid + it * NTHREADS;
        if (g < NGROUPS) {
            int r = g >> 7;             // TW/4 = 128 groups per row
            int c = (g & 127) << 2;
            int idx = (gy0 + r) * IMG_W + gx0 + c;
            float4 R = *(const float4*)(in + idx);
            float4 G = *(const float4*)(in + idx + PLANE);
            float4 B = *(const float4*)(in + idx + 2 * PLANE);
            float4 Y, U, V;
            Y.x = 0.299f*R.x + 0.587f*G.x + 0.114f*B.x;
            Y.y = 0.299f*R.y + 0.587f*G.y + 0.114f*B.y;
            Y.z = 0.299f*R.z + 0.587f*G.z + 0.114f*B.z;
            Y.w = 0.299f*R.w + 0.587f*G.w + 0.114f*B.w;
            U.x = fmaf(-0.168736f,R.x, fmaf(-0.331264f,G.x, fmaf(0.5f,B.x, 128.f)));
            U.y = fmaf(-0.168736f,R.y, fmaf(-0.331264f,G.y, fmaf(0.5f,B.y, 128.f)));
            U.z = fmaf(-0.168736f,R.z, fmaf(-0.331264f,G.z, fmaf(0.5f,B.z, 128.f)));
            U.w = fmaf(-0.168736f,R.w, fmaf(-0.331264f,G.w, fmaf(0.5f,B.w, 128.f)));
            V.x = fmaf(0.5f,R.x, fmaf(-0.418688f,G.x, fmaf(-0.081312f,B.x, 128.f)));
            V.y = fmaf(0.5f,R.y, fmaf(-0.418688f,G.y, fmaf(-0.081312f,B.y, 128.f)));
            V.z = fmaf(0.5f,R.z, fmaf(-0.418688f,G.z, fmaf(-0.081312f,B.z, 128.f)));
            V.w = fmaf(0.5f,R.w, fmaf(-0.418688f,G.w, fmaf(-0.081312f,B.w, 128.f)));
            *(float4*)&s[0][r][c] = Y;
            *(float4*)&s[1][r][c] = U;
            *(float4*)&s[2][r][c] = V;
        }
    }
    __syncthreads();

    // ---------- per-thread 8x8 block: DCT -> quant -> IDCT in registers ----------
    {
        const int ch = tid >> 6;        // 0..2
        const int cb = (tid & 63) << 3; // column base of this thread's block
        const int t  = (ch > 0) ? 1 : 0;

        float m[8][8];
        #pragma unroll
        for (int r = 0; r < 8; ++r) {
            float4 lo = *(float4*)&s[ch][r][cb];
            float4 hi = *(float4*)&s[ch][r][cb + 4];
            m[r][0]=lo.x; m[r][1]=lo.y; m[r][2]=lo.z; m[r][3]=lo.w;
            m[r][4]=hi.x; m[r][5]=hi.y; m[r][6]=hi.z; m[r][7]=hi.w;
        }

        // stage A: column DCT
        #pragma unroll
        for (int c = 0; c < 8; ++c) {
            float v[8];
            #pragma unroll
            for (int j = 0; j < 8; ++j) v[j] = m[j][c];
            fdct8(v);
            #pragma unroll
            for (int j = 0; j < 8; ++j) m[j][c] = v[j];
        }
        // stage B: row DCT + quant/dequant
        #pragma unroll
        for (int r = 0; r < 8; ++r) {
            fdct8(m[r]);
            #pragma unroll
            for (int l = 0; l < 8; ++l) {
                float q  = cQ[t][r * 8 + l];
                float rq = cRQ[t][r * 8 + l];
                float sv = m[r][l];
                float d  = sv * rq;
                float rn = rintf(d);                    // round-half-even
                float e  = fmaf(-rn, q, sv) * rq;       // accurate residual
                m[r][l]  = fmaf(e * e, e, rn) * q;
            }
        }
        // stage C: column IDCT
        #pragma unroll
        for (int c = 0; c < 8; ++c) {
            float v[8];
            #pragma unroll
            for (int j = 0; j < 8; ++j) v[j] = m[j][c];
            idct8(v);
            #pragma unroll
            for (int j = 0; j < 8; ++j) m[j][c] = v[j];
        }
        // stage D: row IDCT
        #pragma unroll
        for (int r = 0; r < 8; ++r) idct8(m[r]);

        #pragma unroll
        for (int r = 0; r < 8; ++r) {
            float4 lo = make_float4(m[r][0], m[r][1], m[r][2], m[r][3]);
            float4 hi = make_float4(m[r][4], m[r][5], m[r][6], m[r][7]);
            *(float4*)&s[ch][r][cb]     = lo;
            *(float4*)&s[ch][r][cb + 4] = hi;
        }
    }
    __syncthreads();

    // ---------- inverse color + normalize + store ----------
    #pragma unroll
    for (int it = 0; it < 6; ++it) {
        int g = tid + it * NTHREADS;
        if (g < NGROUPS) {
            int r = g >> 7;
            int c = (g & 127) << 2;
            float4 Y = *(float4*)&s[0][r][c];
            float4 U = *(float4*)&s[1][r][c];
            float4 V = *(float4*)&s[2][r][c];
            float4 Ro, Go, Bo;
            #pragma unroll
            for (int k = 0; k < 4; ++k) {
                float y = ((float*)&Y)[k];
                float u = ((float*)&U)[k] - 128.0f;
                float v = ((float*)&V)[k] - 128.0f;
                float R = fmaf(IW01, u, fmaf(IW02, v, y));
                float G = fmaf(IW11, u, fmaf(IW12, v, y));
                float B = fmaf(IW21, u, fmaf(IW22, v, y));
                ((float*)&Ro)[k] = (R * (1.0f/255.0f) - MEAN0) * ISTD0;
                ((float*)&Go)[k] = (G * (1.0f/255.0f) - MEAN1) * ISTD1;
                ((float*)&Bo)[k] = (B * (1.0f/255.0f) - MEAN2) * ISTD2;
            }
            int idx = (gy0 + r) * IMG_W + gx0 + c;
            *(float4*)(out + idx)             = Ro;
            *(float4*)(out + idx + PLANE)     = Go;
            *(float4*)(out + idx + 2 * PLANE) = Bo;
        }
    }
}

extern "C" void kernel_launch(void* const* d_in, const int* in_sizes, int n_in,
                              void* d_out, int out_size)
{
    const float* in = (const float*)d_in[0];
    float* out = (float*)d_out;
    dim3 grid(IMG_W / TW, IMG_H / TH);
    jpeg_roundtrip_kernel<<<grid, NTHREADS>>>(in, out);
}